// round 1
// baseline (speedup 1.0000x reference)
#include <cuda_runtime.h>
#include <math.h>

#define BB 8
#define TT 4096
#define NI 64      // I
#define DD 128     // D
#define OO 64      // O
#define PP 8       // P
#define NT (BB*TT) // 32768 rows
#define SEG 128    // scan segment length
#define NS (TT/SEG) // 32 segments per batch

// Scratch (device globals; no allocation allowed)
__device__ float g_hbar[NT * DD];
__device__ float g_z[NT * DD];
__device__ float g_seg[BB * NS * DD];

// ---------------------------------------------------------------------------
// K1: fused APL for h_bar and z (shared interpolation weights).
// grid = (256 row-tiles, 4 d-chunks), 256 threads, 192 KB dyn smem.
// smem: h_tab slice [64][8][32] (64KB) + z_tab slice (64KB) + weights (64KB)
// warp = one row, lane = one channel -> warp-uniform idx => conflict-free LDS.
// ---------------------------------------------------------------------------
#define K1_TILE 128
__global__ void k1_apl_hz(const float* __restrict__ x,
                          const float* __restrict__ hv,
                          const float* __restrict__ zv) {
    extern __shared__ float s[];
    float*  h_s = s;                         // 16384 floats
    float*  z_s = s + 16384;                 // 16384 floats
    float2* w_s = (float2*)(s + 32768);      // 8192 float2 (frac, offset-bits)

    const int tid  = threadIdx.x;
    const int tile = blockIdx.x;             // 0..255
    const int c    = blockIdx.y;             // d-chunk 0..3
    const int n0   = tile * K1_TILE;

    // Load table slices: 512 rows (i*8+p) x 32 floats (d in chunk), float4.
    const float4* hv4 = (const float4*)hv;
    const float4* zv4 = (const float4*)zv;
    float4* hs4 = (float4*)h_s;
    float4* zs4 = (float4*)z_s;
    #pragma unroll
    for (int e = tid; e < 512 * 8; e += 256) {
        int rp = e >> 3, j = e & 7;
        int g = rp * 32 + c * 8 + j;         // global row stride 128 f = 32 f4
        hs4[e] = hv4[g];
        zs4[e] = zv4[g];
    }

    // Precompute (frac, float-offset) per (row, i) once for the tile.
    const float* xrow = x + (size_t)n0 * NI;
    for (int e = tid; e < K1_TILE * NI; e += 256) {
        float xv = xrow[e];
        float t  = fminf(fmaxf((xv + 1.0f) * 3.5f, 0.0f), 7.0f); // (x-lo)/(hi-lo)*(P-1)
        int   idx = min((int)t, 6);
        float f  = t - (float)idx;
        int   i  = e & (NI - 1);
        w_s[e] = make_float2(f, __int_as_float(i * 256 + idx * 32));
    }
    __syncthreads();

    const int wid = tid >> 5, lane = tid & 31;
    #pragma unroll 1
    for (int r = wid * 16; r < wid * 16 + 16; ++r) {
        const float2* wr = w_s + r * NI;
        float acch = 0.0f, accz = 0.0f;
        #pragma unroll 8
        for (int i = 0; i < NI; ++i) {
            float2 w  = wr[i];                       // broadcast LDS.64
            float  f  = w.x;
            int    off = __float_as_int(w.y) + lane;
            float  w0 = 1.0f - f;
            acch = fmaf(w0, h_s[off],      acch);
            acch = fmaf(f,  h_s[off + 32], acch);
            accz = fmaf(w0, z_s[off],      accz);
            accz = fmaf(f,  z_s[off + 32], accz);
        }
        float zz = 1.0f / (1.0f + __expf(-accz));    // sigmoid
        size_t o = (size_t)(n0 + r) * DD + c * 32 + lane;
        g_hbar[o] = acch;
        g_z[o]    = zz;
    }
}

// ---------------------------------------------------------------------------
// K2a: per-segment sums of h_bar. grid = B*NS (256), 128 threads (d).
// ---------------------------------------------------------------------------
__global__ void k2a_segsum() {
    int b = blockIdx.x >> 5;
    int sgi = blockIdx.x & 31;
    int d = threadIdx.x;
    const float* p = g_hbar + ((size_t)b * TT + (size_t)sgi * SEG) * DD + d;
    float a0 = 0.f, a1 = 0.f, a2 = 0.f, a3 = 0.f;
    #pragma unroll 8
    for (int t = 0; t < SEG; t += 4) {
        a0 += p[(t + 0) * DD];
        a1 += p[(t + 1) * DD];
        a2 += p[(t + 2) * DD];
        a3 += p[(t + 3) * DD];
    }
    g_seg[(b * NS + sgi) * DD + d] = (a0 + a1) + (a2 + a3);
}

// ---------------------------------------------------------------------------
// K2b: exclusive scan over segments (seeded with h0). grid = B, 128 threads.
// ---------------------------------------------------------------------------
__global__ void k2b_scan(const float* __restrict__ h0) {
    int b = blockIdx.x, d = threadIdx.x;
    float run = h0[b * DD + d];
    float* p = g_seg + (size_t)b * NS * DD + d;
    #pragma unroll
    for (int sgi = 0; sgi < NS; ++sgi) {
        float v = p[sgi * DD];
        p[sgi * DD] = run;
        run += v;
    }
}

// ---------------------------------------------------------------------------
// K2c: ht = (1-z)*(cumsum+h0) + z*h_bar = c + z*(h_bar - c). grid = B*NS.
// ---------------------------------------------------------------------------
__global__ void k2c_ht(float* __restrict__ out_ht) {
    int b = blockIdx.x >> 5;
    int sgi = blockIdx.x & 31;
    int d = threadIdx.x;
    float c = g_seg[(b * NS + sgi) * DD + d];
    size_t base = ((size_t)b * TT + (size_t)sgi * SEG) * DD + d;
    #pragma unroll 4
    for (int t = 0; t < SEG; ++t) {
        float hb = g_hbar[base + (size_t)t * DD];
        float zz = g_z[base + (size_t)t * DD];
        c += hb;
        out_ht[base + (size_t)t * DD] = fmaf(zz, hb - c, c);
    }
}

// ---------------------------------------------------------------------------
// K3: output APL  y = apl(ht, out_values).
// grid = (512 row-tiles, 2 o-chunks), 256 threads, 192 KB dyn smem.
// smem: out_values slice [128][8][32] (128KB) + weights 64x128 float2 (64KB)
// ---------------------------------------------------------------------------
#define K3_TILE 64
__global__ void k3_apl_out(const float* __restrict__ ht,
                           const float* __restrict__ ov,
                           float* __restrict__ y) {
    extern __shared__ float s[];
    float*  o_s = s;                        // 32768 floats (128 KB)
    float2* w_s = (float2*)(s + 32768);     // 8192 float2 (64 KB)

    const int tid  = threadIdx.x;
    const int tile = blockIdx.x;            // 0..511
    const int oc   = blockIdx.y;            // 0..1
    const int n0   = tile * K3_TILE;

    const float4* ov4 = (const float4*)ov;
    float4* os4 = (float4*)o_s;
    #pragma unroll
    for (int e = tid; e < 1024 * 8; e += 256) {     // 1024 rows (d*8+p) x 8 f4
        int rp = e >> 3, j = e & 7;
        os4[e] = ov4[rp * 16 + oc * 8 + j];         // global row stride 64 f = 16 f4
    }
    const float* hrow = ht + (size_t)n0 * DD;
    for (int e = tid; e < K3_TILE * DD; e += 256) {
        float xv = hrow[e];
        float t  = fminf(fmaxf((xv + 1.0f) * 3.5f, 0.0f), 7.0f);
        int   idx = min((int)t, 6);
        float f  = t - (float)idx;
        int   i  = e & (DD - 1);
        w_s[e] = make_float2(f, __int_as_float(i * 256 + idx * 32));
    }
    __syncthreads();

    const int wid = tid >> 5, lane = tid & 31;
    #pragma unroll 1
    for (int r = wid * 8; r < wid * 8 + 8; ++r) {
        const float2* wr = w_s + r * DD;
        float acc = 0.0f;
        #pragma unroll 8
        for (int i = 0; i < DD; ++i) {
            float2 w = wr[i];
            int off = __float_as_int(w.y) + lane;
            acc = fmaf(1.0f - w.x, o_s[off],      acc);
            acc = fmaf(w.x,        o_s[off + 32], acc);
        }
        y[(size_t)(n0 + r) * OO + oc * 32 + lane] = acc;
    }
}

// ---------------------------------------------------------------------------
extern "C" void kernel_launch(void* const* d_in, const int* in_sizes, int n_in,
                              void* d_out, int out_size) {
    const float* x  = (const float*)d_in[0];   // (B,T,I)
    const float* h0 = (const float*)d_in[1];   // (B,D)
    const float* zv = (const float*)d_in[2];   // (I,P,D)
    const float* hv = (const float*)d_in[3];   // (I,P,D)
    const float* ov = (const float*)d_in[4];   // (D,P,O)

    float* y  = (float*)d_out;                      // (B,T,O)
    float* ht = (float*)d_out + (size_t)NT * OO;    // (B,T,D)

    cudaFuncSetAttribute(k1_apl_hz,  cudaFuncAttributeMaxDynamicSharedMemorySize, 196608);
    cudaFuncSetAttribute(k3_apl_out, cudaFuncAttributeMaxDynamicSharedMemorySize, 196608);

    k1_apl_hz<<<dim3(256, 4), 256, 196608>>>(x, hv, zv);
    k2a_segsum<<<256, 128>>>();
    k2b_scan<<<BB, 128>>>(h0);
    k2c_ht<<<256, 128>>>(ht);
    k3_apl_out<<<dim3(512, 2), 256, 196608>>>(ht, ov, y);
}

// round 3
// speedup vs baseline: 1.1505x; 1.1505x over previous
#include <cuda_runtime.h>
#include <cuda_fp16.h>
#include <stdint.h>

#define BB 8
#define TT 4096
#define NI 64
#define DD 128
#define OO 64
#define NT (BB*TT)          // 32768 rows
#define SEG 32
#define NSEG (NT/SEG)       // 1024 segments

// ------------------------- scratch (device globals) -------------------------
__device__ float g_hbar[NT*DD];
__device__ float g_z[NT*DD];
__device__ float g_seg[NSEG*DD];
__device__ uint4 g_bf1[32*32*32];   // stage1 B frags: [K=32][ntg=32][lane=32] {hi0,hi1,lo0,lo1}
__device__ uint4 g_bf3[64*8*32];    // stage3 B frags: [K=64][ntg=8][lane=32]

// ------------------------- helpers -------------------------
static __device__ __forceinline__ float clip7(float x){
  return fminf(fmaxf((x + 1.0f) * 3.5f, 0.0f), 7.0f);
}
static __device__ __forceinline__ float hatf(float t, float p){
  return fmaxf(0.0f, 1.0f - fabsf(t - p));
}
// pack (a,b) into fp16 hi half2 + residual lo half2
static __device__ __forceinline__ void pack_hl(float a, float b, uint32_t& hi, uint32_t& lo){
  __half2 h = __floats2half2_rn(a, b);
  float2  f = __half22float2(h);
  __half2 l = __floats2half2_rn(a - f.x, b - f.y);
  hi = *reinterpret_cast<uint32_t*>(&h);
  lo = *reinterpret_cast<uint32_t*>(&l);
}
static __device__ __forceinline__ void mma16816(float* c, const uint32_t* a, uint32_t b0, uint32_t b1){
  asm volatile(
    "mma.sync.aligned.m16n8k16.row.col.f32.f16.f16.f32 "
    "{%0,%1,%2,%3}, {%4,%5,%6,%7}, {%8,%9}, {%0,%1,%2,%3};"
    : "+f"(c[0]), "+f"(c[1]), "+f"(c[2]), "+f"(c[3])
    : "r"(a[0]), "r"(a[1]), "r"(a[2]), "r"(a[3]), "r"(b0), "r"(b1));
}

// ------------------------- k0: build fragment-major B tables (x16 scale) -------------------------
__global__ void k0_prep(const float* __restrict__ zv, const float* __restrict__ hv,
                        const float* __restrict__ ov){
  int t = blockIdx.x * blockDim.x + threadIdx.x;
  if (t < 32*32*32){
    int lane = t & 31, ntg = (t >> 5) & 31, K = t >> 10;
    int q = lane & 3, g = lane >> 2;
    int n  = ntg * 8 + g;                 // 0..255
    int kr = q * 2;                       // p base
    const float* tab = (n < 128) ? hv : zv;
    int nn = n & 127;
    int i0 = 2 * K;
    float v0 = tab[((i0    )*8 + kr    )*128 + nn] * 16.0f;  // b0: (i0, kr)
    float v1 = tab[((i0    )*8 + kr + 1)*128 + nn] * 16.0f;  // b1: (i0, kr+1)
    float v2 = tab[((i0 + 1)*8 + kr    )*128 + nn] * 16.0f;  // b2: (i0+1, kr)
    float v3 = tab[((i0 + 1)*8 + kr + 1)*128 + nn] * 16.0f;  // b3
    uint4 o;
    pack_hl(v0, v1, o.x, o.z);
    pack_hl(v2, v3, o.y, o.w);
    g_bf1[t] = o;
  } else if (t < 32*32*32 + 64*8*32){
    int e = t - 32*32*32;
    int lane = e & 31, ntg = (e >> 5) & 7, K = e >> 8;
    int q = lane & 3, g = lane >> 2;
    int n  = ntg * 8 + g;                 // 0..63
    int kr = q * 2;
    int i0 = 2 * K;                       // d-input index
    float v0 = ov[((i0    )*8 + kr    )*64 + n] * 16.0f;
    float v1 = ov[((i0    )*8 + kr + 1)*64 + n] * 16.0f;
    float v2 = ov[((i0 + 1)*8 + kr    )*64 + n] * 16.0f;
    float v3 = ov[((i0 + 1)*8 + kr + 1)*64 + n] * 16.0f;
    uint4 o;
    pack_hl(v0, v1, o.x, o.z);
    pack_hl(v2, v3, o.y, o.w);
    g_bf3[e] = o;
  }
}

// ------------------------- K1: stage-1 HMMA GEMM (h_bar + z) -------------------------
// CTA: 128 thr = 4 warps; warp (mr, nc): mr in {0,1} -> 32 rows, nc in {0,1} -> 128 cols (h / z).
// M per CTA = 64 -> grid 512.
#define SW1 66
__global__ void __launch_bounds__(128) k1_mma(const float* __restrict__ x){
  __shared__ float t_s[64 * SW1];
  const int tid = threadIdx.x;
  const int n0  = blockIdx.x * 64;

  // prepass: t = clip grid coords for the 64x64 x-tile
  #pragma unroll
  for (int e = tid; e < 64 * 16; e += 128){
    int r = e >> 4, c4 = e & 15;
    float4 v = ((const float4*)(x + (size_t)(n0 + r) * NI))[c4];
    float* d = &t_s[r * SW1 + c4 * 4];
    d[0] = clip7(v.x); d[1] = clip7(v.y); d[2] = clip7(v.z); d[3] = clip7(v.w);
  }
  __syncthreads();

  const int w = tid >> 5, lane = tid & 31;
  const int mr = w & 1, nc = w >> 1;
  const int rowbase = mr * 32;
  const int q = lane & 3, g = lane >> 2;
  const float p0 = (float)(2 * q);

  float acc[2][16][4];
  #pragma unroll
  for (int a = 0; a < 2; ++a)
    #pragma unroll
    for (int b = 0; b < 16; ++b)
      #pragma unroll
      for (int c = 0; c < 4; ++c) acc[a][b][c] = 0.0f;

  #pragma unroll 1
  for (int K = 0; K < 32; ++K){
    const int i0 = 2 * K;
    uint32_t ah[2][4], al[2][4];
    #pragma unroll
    for (int mt = 0; mt < 2; ++mt){
      int r0 = rowbase + mt * 16 + g;
      float2 tA = *(const float2*)&t_s[ r0      * SW1 + i0];
      float2 tB = *(const float2*)&t_s[(r0 + 8) * SW1 + i0];
      pack_hl(hatf(tA.x, p0), hatf(tA.x, p0 + 1.0f), ah[mt][0], al[mt][0]);
      pack_hl(hatf(tB.x, p0), hatf(tB.x, p0 + 1.0f), ah[mt][1], al[mt][1]);
      pack_hl(hatf(tA.y, p0), hatf(tA.y, p0 + 1.0f), ah[mt][2], al[mt][2]);
      pack_hl(hatf(tB.y, p0), hatf(tB.y, p0 + 1.0f), ah[mt][3], al[mt][3]);
    }
    const uint4* bp = g_bf1 + ((size_t)K * 32 + nc * 16) * 32 + lane;
    #pragma unroll 8
    for (int nt = 0; nt < 16; ++nt){
      uint4 bv = __ldg(bp + nt * 32);
      #pragma unroll
      for (int mt = 0; mt < 2; ++mt){
        mma16816(acc[mt][nt], ah[mt], bv.x, bv.y);   // Ah * Bh
        mma16816(acc[mt][nt], ah[mt], bv.z, bv.w);   // Ah * Bl
        mma16816(acc[mt][nt], al[mt], bv.x, bv.y);   // Al * Bh
      }
    }
  }

  // epilogue: scale 1/16; nc=0 -> g_hbar + segment sums; nc=1 -> sigmoid -> g_z
  const float sc = 0.0625f;
  const int sgi = blockIdx.x * 2 + mr;   // 32-row segment index
  #pragma unroll
  for (int nt = 0; nt < 16; ++nt){
    const int col = nt * 8 + q * 2;
    float s0 = 0.0f, s1 = 0.0f;
    #pragma unroll
    for (int mt = 0; mt < 2; ++mt){
      float c0 = acc[mt][nt][0] * sc, c1 = acc[mt][nt][1] * sc;
      float c2 = acc[mt][nt][2] * sc, c3 = acc[mt][nt][3] * sc;
      int rg = n0 + rowbase + mt * 16 + g;
      if (nc){
        c0 = 1.0f / (1.0f + __expf(-c0)); c1 = 1.0f / (1.0f + __expf(-c1));
        c2 = 1.0f / (1.0f + __expf(-c2)); c3 = 1.0f / (1.0f + __expf(-c3));
        *(float2*)&g_z[(size_t) rg      * DD + col] = make_float2(c0, c1);
        *(float2*)&g_z[(size_t)(rg + 8) * DD + col] = make_float2(c2, c3);
      } else {
        *(float2*)&g_hbar[(size_t) rg      * DD + col] = make_float2(c0, c1);
        *(float2*)&g_hbar[(size_t)(rg + 8) * DD + col] = make_float2(c2, c3);
        s0 += c0 + c2; s1 += c1 + c3;
      }
    }
    if (!nc){
      #pragma unroll
      for (int off = 4; off < 32; off <<= 1){
        s0 += __shfl_xor_sync(0xFFFFFFFFu, s0, off);
        s1 += __shfl_xor_sync(0xFFFFFFFFu, s1, off);
      }
      if (g == 0)
        *(float2*)&g_seg[(size_t)sgi * DD + col] = make_float2(s0, s1);
    }
  }
}

// ------------------------- k2b: exclusive scan over segments (per batch) -------------------------
__global__ void k2b_scan(const float* __restrict__ h0){
  int b = blockIdx.x, d = threadIdx.x;
  float run = h0[b * DD + d];
  float* p = g_seg + (size_t)b * (TT / SEG) * DD + d;
  #pragma unroll 1
  for (int gq = 0; gq < (TT / SEG) / 8; ++gq){
    float v[8];
    #pragma unroll
    for (int j = 0; j < 8; ++j) v[j] = p[(gq * 8 + j) * DD];
    #pragma unroll
    for (int j = 0; j < 8; ++j){ float t = v[j]; p[(gq * 8 + j) * DD] = run; run += t; }
  }
}

// ------------------------- k2c: ht = c + z*(h_bar - c) -------------------------
__global__ void __launch_bounds__(128) k2c_ht(float* __restrict__ out_ht){
  int si = blockIdx.x, d = threadIdx.x;
  float c = g_seg[(size_t)si * DD + d];
  size_t base = (size_t)si * SEG * DD + d;
  #pragma unroll
  for (int t0 = 0; t0 < SEG; t0 += 8){
    float hb[8], zz[8];
    #pragma unroll
    for (int j = 0; j < 8; ++j){
      hb[j] = g_hbar[base + (size_t)(t0 + j) * DD];
      zz[j] = g_z  [base + (size_t)(t0 + j) * DD];
    }
    #pragma unroll
    for (int j = 0; j < 8; ++j){
      c += hb[j];
      out_ht[base + (size_t)(t0 + j) * DD] = fmaf(zz[j], hb[j] - c, c);
    }
  }
}

// ------------------------- K3: stage-3 HMMA GEMM (y) -------------------------
// CTA: 128 thr = 4 warps; warp mr in {0..3} -> 32 rows, all 64 cols. M per CTA = 128 -> grid 256.
#define SW3 130
__global__ void __launch_bounds__(128) k3_mma(const float* __restrict__ ht,
                                              float* __restrict__ y){
  extern __shared__ float t3_s[];       // 128 x SW3
  const int tid = threadIdx.x;
  const int n0  = blockIdx.x * 128;

  #pragma unroll 1
  for (int e = tid; e < 128 * 32; e += 128){
    int r = e >> 5, c4 = e & 31;
    float4 v = ((const float4*)(ht + (size_t)(n0 + r) * DD))[c4];
    float* d = &t3_s[r * SW3 + c4 * 4];
    d[0] = clip7(v.x); d[1] = clip7(v.y); d[2] = clip7(v.z); d[3] = clip7(v.w);
  }
  __syncthreads();

  const int mr = tid >> 5, lane = tid & 31;
  const int rowbase = mr * 32;
  const int q = lane & 3, g = lane >> 2;
  const float p0 = (float)(2 * q);

  float acc[2][8][4];
  #pragma unroll
  for (int a = 0; a < 2; ++a)
    #pragma unroll
    for (int b = 0; b < 8; ++b)
      #pragma unroll
      for (int c = 0; c < 4; ++c) acc[a][b][c] = 0.0f;

  #pragma unroll 1
  for (int K = 0; K < 64; ++K){
    const int i0 = 2 * K;
    uint32_t ah[2][4], al[2][4];
    #pragma unroll
    for (int mt = 0; mt < 2; ++mt){
      int r0 = rowbase + mt * 16 + g;
      float2 tA = *(const float2*)&t3_s[ r0      * SW3 + i0];
      float2 tB = *(const float2*)&t3_s[(r0 + 8) * SW3 + i0];
      pack_hl(hatf(tA.x, p0), hatf(tA.x, p0 + 1.0f), ah[mt][0], al[mt][0]);
      pack_hl(hatf(tB.x, p0), hatf(tB.x, p0 + 1.0f), ah[mt][1], al[mt][1]);
      pack_hl(hatf(tA.y, p0), hatf(tA.y, p0 + 1.0f), ah[mt][2], al[mt][2]);
      pack_hl(hatf(tB.y, p0), hatf(tB.y, p0 + 1.0f), ah[mt][3], al[mt][3]);
    }
    const uint4* bp = g_bf3 + (size_t)K * 8 * 32 + lane;
    #pragma unroll
    for (int nt = 0; nt < 8; ++nt){
      uint4 bv = __ldg(bp + nt * 32);
      #pragma unroll
      for (int mt = 0; mt < 2; ++mt){
        mma16816(acc[mt][nt], ah[mt], bv.x, bv.y);
        mma16816(acc[mt][nt], ah[mt], bv.z, bv.w);
        mma16816(acc[mt][nt], al[mt], bv.x, bv.y);
      }
    }
  }

  const float sc = 0.0625f;
  #pragma unroll
  for (int nt = 0; nt < 8; ++nt){
    const int col = nt * 8 + q * 2;
    #pragma unroll
    for (int mt = 0; mt < 2; ++mt){
      int rg = n0 + rowbase + mt * 16 + g;
      *(float2*)&y[(size_t) rg      * OO + col] =
          make_float2(acc[mt][nt][0] * sc, acc[mt][nt][1] * sc);
      *(float2*)&y[(size_t)(rg + 8) * OO + col] =
          make_float2(acc[mt][nt][2] * sc, acc[mt][nt][3] * sc);
    }
  }
}

// ------------------------- host -------------------------
extern "C" void kernel_launch(void* const* d_in, const int* in_sizes, int n_in,
                              void* d_out, int out_size) {
  const float* x  = (const float*)d_in[0];   // (B,T,I)
  const float* h0 = (const float*)d_in[1];   // (B,D)
  const float* zv = (const float*)d_in[2];   // (I,P,D)
  const float* hv = (const float*)d_in[3];   // (I,P,D)
  const float* ov = (const float*)d_in[4];   // (D,P,O)

  float* y  = (float*)d_out;                     // (B,T,O)
  float* ht = (float*)d_out + (size_t)NT * OO;   // (B,T,D)

  cudaFuncSetAttribute(k3_mma, cudaFuncAttributeMaxDynamicSharedMemorySize, 128 * SW3 * 4);

  k0_prep<<<(32*32*32 + 64*8*32 + 255) / 256, 256>>>(zv, hv, ov);
  k1_mma<<<512, 128>>>(x);
  k2b_scan<<<BB, DD>>>(h0);
  k2c_ht<<<NSEG, DD>>>(ht);
  k3_mma<<<256, 128, 128 * SW3 * 4>>>(ht, y);
}

// round 4
// speedup vs baseline: 2.2293x; 1.9376x over previous
#include <cuda_runtime.h>
#include <cuda_fp16.h>
#include <stdint.h>

#define BB 8
#define TT 4096
#define NI 64
#define DD 128
#define OO 64
#define NT (BB*TT)          // 32768 rows
#define SEG 32
#define NSEG (NT/SEG)       // 1024 segments

// ------------------------- scratch (device globals) -------------------------
__device__ float g_hbar[NT*DD];
__device__ float g_z[NT*DD];
__device__ float g_seg[NSEG*DD];
__device__ uint4 g_bf1[32*32*32];   // stage1 B frags: [K=32][ntg=32][lane=32] {hi0,hi1,lo0,lo1}
__device__ uint4 g_bf3[64*8*32];    // stage3 B frags: [K=64][ntg=8][lane=32]

// ------------------------- helpers -------------------------
static __device__ __forceinline__ float clip7(float x){
  return fminf(fmaxf((x + 1.0f) * 3.5f, 0.0f), 7.0f);
}
static __device__ __forceinline__ float hatf(float t, float p){
  return fmaxf(0.0f, 1.0f - fabsf(t - p));
}
static __device__ __forceinline__ void pack_hl(float a, float b, uint32_t& hi, uint32_t& lo){
  __half2 h = __floats2half2_rn(a, b);
  float2  f = __half22float2(h);
  __half2 l = __floats2half2_rn(a - f.x, b - f.y);
  hi = *reinterpret_cast<uint32_t*>(&h);
  lo = *reinterpret_cast<uint32_t*>(&l);
}
static __device__ __forceinline__ void mma16816(float* c, const uint32_t* a, uint32_t b0, uint32_t b1){
  asm volatile(
    "mma.sync.aligned.m16n8k16.row.col.f32.f16.f16.f32 "
    "{%0,%1,%2,%3}, {%4,%5,%6,%7}, {%8,%9}, {%0,%1,%2,%3};"
    : "+f"(c[0]), "+f"(c[1]), "+f"(c[2]), "+f"(c[3])
    : "r"(a[0]), "r"(a[1]), "r"(a[2]), "r"(a[3]), "r"(b0), "r"(b1));
}
static __device__ __forceinline__ uint32_t smem_u32(const void* p){
  uint32_t a;
  asm("{ .reg .u64 t; cvta.to.shared.u64 t, %1; cvt.u32.u64 %0, t; }" : "=r"(a) : "l"(p));
  return a;
}
static __device__ __forceinline__ void cpa16(uint32_t sa, const void* g){
  asm volatile("cp.async.cg.shared.global [%0], [%1], 16;" :: "r"(sa), "l"(g));
}
#define CPA_COMMIT()  asm volatile("cp.async.commit_group;" ::: "memory")
#define CPA_WAIT1()   asm volatile("cp.async.wait_group 1;" ::: "memory")

// ------------------------- k0: build fragment-major B tables (x16 scale) -------------------------
__global__ void k0_prep(const float* __restrict__ zv, const float* __restrict__ hv,
                        const float* __restrict__ ov){
  int t = blockIdx.x * blockDim.x + threadIdx.x;
  if (t < 32*32*32){
    int lane = t & 31, ntg = (t >> 5) & 31, K = t >> 10;
    int q = lane & 3, g = lane >> 2;
    int n  = ntg * 8 + g;
    int kr = q * 2;
    const float* tab = (n < 128) ? hv : zv;
    int nn = n & 127;
    int i0 = 2 * K;
    float v0 = tab[((i0    )*8 + kr    )*128 + nn] * 16.0f;
    float v1 = tab[((i0    )*8 + kr + 1)*128 + nn] * 16.0f;
    float v2 = tab[((i0 + 1)*8 + kr    )*128 + nn] * 16.0f;
    float v3 = tab[((i0 + 1)*8 + kr + 1)*128 + nn] * 16.0f;
    uint4 o;
    pack_hl(v0, v1, o.x, o.z);
    pack_hl(v2, v3, o.y, o.w);
    g_bf1[t] = o;
  } else if (t < 32*32*32 + 64*8*32){
    int e = t - 32*32*32;
    int lane = e & 31, ntg = (e >> 5) & 7, K = e >> 8;
    int q = lane & 3, g = lane >> 2;
    int n  = ntg * 8 + g;
    int kr = q * 2;
    int i0 = 2 * K;
    float v0 = ov[((i0    )*8 + kr    )*64 + n] * 16.0f;
    float v1 = ov[((i0    )*8 + kr + 1)*64 + n] * 16.0f;
    float v2 = ov[((i0 + 1)*8 + kr    )*64 + n] * 16.0f;
    float v3 = ov[((i0 + 1)*8 + kr + 1)*64 + n] * 16.0f;
    uint4 o;
    pack_hl(v0, v1, o.x, o.z);
    pack_hl(v2, v3, o.y, o.w);
    g_bf3[e] = o;
  }
}

// ------------------------- K1: stage-1 HMMA GEMM (h_bar + z), cp.async pipelined -------------------------
// CTA: 128 thr = 4 warps; warp (mr, nc): mr -> 32 rows, nc -> 128 cols (h / z). M/CTA=64 -> grid 512.
// smem: t_s 64x66 f32 (16896B) + B ring 3 x 16KB = 66048B total.
#define SW1 66
__global__ void __launch_bounds__(128) k1_mma(const float* __restrict__ x){
  extern __shared__ char smraw[];
  float* t_s = (float*)smraw;
  uint4* bbuf = (uint4*)(smraw + 64 * SW1 * 4);
  const uint32_t bbase = smem_u32(bbuf);

  const int tid = threadIdx.x;
  const int n0  = blockIdx.x * 64;

  // prologue: start copies for K=0,1 immediately (overlap with prepass)
  #pragma unroll
  for (int s = 0; s < 2; ++s){
    uint32_t sa = bbase + (uint32_t)(s * 1024 + tid) * 16u;
    const uint4* gs = g_bf1 + (size_t)s * 1024 + tid;
    #pragma unroll
    for (int j = 0; j < 8; ++j) cpa16(sa + j * 128 * 16, gs + j * 128);
    CPA_COMMIT();
  }

  // prepass: t = clipped grid coords for the 64x64 x-tile
  #pragma unroll
  for (int e = tid; e < 64 * 16; e += 128){
    int r = e >> 4, c4 = e & 15;
    float4 v = ((const float4*)(x + (size_t)(n0 + r) * NI))[c4];
    float* d = &t_s[r * SW1 + c4 * 4];
    d[0] = clip7(v.x); d[1] = clip7(v.y); d[2] = clip7(v.z); d[3] = clip7(v.w);
  }
  __syncthreads();

  const int w = tid >> 5, lane = tid & 31;
  const int mr = w & 1, nc = w >> 1;
  const int rowbase = mr * 32;
  const int q = lane & 3, g = lane >> 2;
  const float p0 = (float)(2 * q);

  float acc[2][16][4];
  #pragma unroll
  for (int a = 0; a < 2; ++a)
    #pragma unroll
    for (int b = 0; b < 16; ++b)
      #pragma unroll
      for (int c = 0; c < 4; ++c) acc[a][b][c] = 0.0f;

  #pragma unroll 1
  for (int K = 0; K < 32; ++K){
    // A-build first: overlaps in-flight cp.async
    const int i0 = 2 * K;
    uint32_t ah[2][4], al[2][4];
    #pragma unroll
    for (int mt = 0; mt < 2; ++mt){
      int r0 = rowbase + mt * 16 + g;
      float2 tA = *(const float2*)&t_s[ r0      * SW1 + i0];
      float2 tB = *(const float2*)&t_s[(r0 + 8) * SW1 + i0];
      pack_hl(hatf(tA.x, p0), hatf(tA.x, p0 + 1.0f), ah[mt][0], al[mt][0]);
      pack_hl(hatf(tB.x, p0), hatf(tB.x, p0 + 1.0f), ah[mt][1], al[mt][1]);
      pack_hl(hatf(tA.y, p0), hatf(tA.y, p0 + 1.0f), ah[mt][2], al[mt][2]);
      pack_hl(hatf(tB.y, p0), hatf(tB.y, p0 + 1.0f), ah[mt][3], al[mt][3]);
    }

    CPA_WAIT1();          // stage K landed
    __syncthreads();      // visible to all warps; prior stage fully consumed

    if (K + 2 < 32){      // issue copy for K+2 into ring slot (K+2)%3 == (K-1)%3
      int s = (K + 2) % 3;
      uint32_t sa = bbase + (uint32_t)(s * 1024 + tid) * 16u;
      const uint4* gs = g_bf1 + (size_t)(K + 2) * 1024 + tid;
      #pragma unroll
      for (int j = 0; j < 8; ++j) cpa16(sa + j * 128 * 16, gs + j * 128);
      CPA_COMMIT();
    }

    const uint4* bs = bbuf + (K % 3) * 1024 + nc * 512 + lane;
    uint4 bv = bs[0];
    #pragma unroll
    for (int nt = 0; nt < 16; ++nt){
      uint4 nb;
      if (nt < 15) nb = bs[(nt + 1) * 32];
      #pragma unroll
      for (int mt = 0; mt < 2; ++mt){
        mma16816(acc[mt][nt], ah[mt], bv.x, bv.y);   // Ah*Bh
        mma16816(acc[mt][nt], ah[mt], bv.z, bv.w);   // Ah*Bl
        mma16816(acc[mt][nt], al[mt], bv.x, bv.y);   // Al*Bh
      }
      if (nt < 15) bv = nb;
    }
  }

  // epilogue: scale 1/16; nc=0 -> g_hbar + segment sums; nc=1 -> sigmoid -> g_z
  const float sc = 0.0625f;
  const int sgi = blockIdx.x * 2 + mr;
  #pragma unroll
  for (int nt = 0; nt < 16; ++nt){
    const int col = nt * 8 + q * 2;
    float s0 = 0.0f, s1 = 0.0f;
    #pragma unroll
    for (int mt = 0; mt < 2; ++mt){
      float c0 = acc[mt][nt][0] * sc, c1 = acc[mt][nt][1] * sc;
      float c2 = acc[mt][nt][2] * sc, c3 = acc[mt][nt][3] * sc;
      int rg = n0 + rowbase + mt * 16 + g;
      if (nc){
        c0 = 1.0f / (1.0f + __expf(-c0)); c1 = 1.0f / (1.0f + __expf(-c1));
        c2 = 1.0f / (1.0f + __expf(-c2)); c3 = 1.0f / (1.0f + __expf(-c3));
        *(float2*)&g_z[(size_t) rg      * DD + col] = make_float2(c0, c1);
        *(float2*)&g_z[(size_t)(rg + 8) * DD + col] = make_float2(c2, c3);
      } else {
        *(float2*)&g_hbar[(size_t) rg      * DD + col] = make_float2(c0, c1);
        *(float2*)&g_hbar[(size_t)(rg + 8) * DD + col] = make_float2(c2, c3);
        s0 += c0 + c2; s1 += c1 + c3;
      }
    }
    if (!nc){
      #pragma unroll
      for (int off = 4; off < 32; off <<= 1){
        s0 += __shfl_xor_sync(0xFFFFFFFFu, s0, off);
        s1 += __shfl_xor_sync(0xFFFFFFFFu, s1, off);
      }
      if (g == 0)
        *(float2*)&g_seg[(size_t)sgi * DD + col] = make_float2(s0, s1);
    }
  }
}

// ------------------------- k2b: exclusive scan over segments (per batch) -------------------------
__global__ void k2b_scan(const float* __restrict__ h0){
  int b = blockIdx.x, d = threadIdx.x;
  float run = h0[b * DD + d];
  float* p = g_seg + (size_t)b * (TT / SEG) * DD + d;
  #pragma unroll 1
  for (int gq = 0; gq < (TT / SEG) / 8; ++gq){
    float v[8];
    #pragma unroll
    for (int j = 0; j < 8; ++j) v[j] = p[(gq * 8 + j) * DD];
    #pragma unroll
    for (int j = 0; j < 8; ++j){ float t = v[j]; p[(gq * 8 + j) * DD] = run; run += t; }
  }
}

// ------------------------- k2c: ht = c + z*(h_bar - c) -------------------------
__global__ void __launch_bounds__(128) k2c_ht(float* __restrict__ out_ht){
  int si = blockIdx.x, d = threadIdx.x;
  float c = g_seg[(size_t)si * DD + d];
  size_t base = (size_t)si * SEG * DD + d;
  #pragma unroll
  for (int t0 = 0; t0 < SEG; t0 += 8){
    float hb[8], zz[8];
    #pragma unroll
    for (int j = 0; j < 8; ++j){
      hb[j] = g_hbar[base + (size_t)(t0 + j) * DD];
      zz[j] = g_z  [base + (size_t)(t0 + j) * DD];
    }
    #pragma unroll
    for (int j = 0; j < 8; ++j){
      c += hb[j];
      out_ht[base + (size_t)(t0 + j) * DD] = fmaf(zz[j], hb[j] - c, c);
    }
  }
}

// ------------------------- K3: stage-3 HMMA GEMM (y), cp.async pipelined -------------------------
// CTA: 128 thr = 4 warps; warp mr -> 32 rows, all 64 cols. M/CTA=128 -> grid 256.
// smem: t3_s 128x130 f32 (66560B) + B ring 3 x 4KB = 78848B total.
#define SW3 130
__global__ void __launch_bounds__(128) k3_mma(const float* __restrict__ ht,
                                              float* __restrict__ y){
  extern __shared__ char smraw[];
  float* t3_s = (float*)smraw;
  uint4* bbuf = (uint4*)(smraw + 128 * SW3 * 4);
  const uint32_t bbase = smem_u32(bbuf);

  const int tid = threadIdx.x;
  const int n0  = blockIdx.x * 128;

  #pragma unroll
  for (int s = 0; s < 2; ++s){
    uint32_t sa = bbase + (uint32_t)(s * 256 + tid) * 16u;
    const uint4* gs = g_bf3 + (size_t)s * 256 + tid;
    #pragma unroll
    for (int j = 0; j < 2; ++j) cpa16(sa + j * 128 * 16, gs + j * 128);
    CPA_COMMIT();
  }

  #pragma unroll 1
  for (int e = tid; e < 128 * 32; e += 128){
    int r = e >> 5, c4 = e & 31;
    float4 v = ((const float4*)(ht + (size_t)(n0 + r) * DD))[c4];
    float* d = &t3_s[r * SW3 + c4 * 4];
    d[0] = clip7(v.x); d[1] = clip7(v.y); d[2] = clip7(v.z); d[3] = clip7(v.w);
  }
  __syncthreads();

  const int mr = tid >> 5, lane = tid & 31;
  const int rowbase = mr * 32;
  const int q = lane & 3, g = lane >> 2;
  const float p0 = (float)(2 * q);

  float acc[2][8][4];
  #pragma unroll
  for (int a = 0; a < 2; ++a)
    #pragma unroll
    for (int b = 0; b < 8; ++b)
      #pragma unroll
      for (int c = 0; c < 4; ++c) acc[a][b][c] = 0.0f;

  #pragma unroll 1
  for (int K = 0; K < 64; ++K){
    const int i0 = 2 * K;
    uint32_t ah[2][4], al[2][4];
    #pragma unroll
    for (int mt = 0; mt < 2; ++mt){
      int r0 = rowbase + mt * 16 + g;
      float2 tA = *(const float2*)&t3_s[ r0      * SW3 + i0];
      float2 tB = *(const float2*)&t3_s[(r0 + 8) * SW3 + i0];
      pack_hl(hatf(tA.x, p0), hatf(tA.x, p0 + 1.0f), ah[mt][0], al[mt][0]);
      pack_hl(hatf(tB.x, p0), hatf(tB.x, p0 + 1.0f), ah[mt][1], al[mt][1]);
      pack_hl(hatf(tA.y, p0), hatf(tA.y, p0 + 1.0f), ah[mt][2], al[mt][2]);
      pack_hl(hatf(tB.y, p0), hatf(tB.y, p0 + 1.0f), ah[mt][3], al[mt][3]);
    }

    CPA_WAIT1();
    __syncthreads();

    if (K + 2 < 64){
      int s = (K + 2) % 3;
      uint32_t sa = bbase + (uint32_t)(s * 256 + tid) * 16u;
      const uint4* gs = g_bf3 + (size_t)(K + 2) * 256 + tid;
      #pragma unroll
      for (int j = 0; j < 2; ++j) cpa16(sa + j * 128 * 16, gs + j * 128);
      CPA_COMMIT();
    }

    const uint4* bs = bbuf + (K % 3) * 256 + lane;
    uint4 bv = bs[0];
    #pragma unroll
    for (int nt = 0; nt < 8; ++nt){
      uint4 nb;
      if (nt < 7) nb = bs[(nt + 1) * 32];
      #pragma unroll
      for (int mt = 0; mt < 2; ++mt){
        mma16816(acc[mt][nt], ah[mt], bv.x, bv.y);
        mma16816(acc[mt][nt], ah[mt], bv.z, bv.w);
        mma16816(acc[mt][nt], al[mt], bv.x, bv.y);
      }
      if (nt < 7) bv = nb;
    }
  }

  const float sc = 0.0625f;
  #pragma unroll
  for (int nt = 0; nt < 8; ++nt){
    const int col = nt * 8 + q * 2;
    #pragma unroll
    for (int mt = 0; mt < 2; ++mt){
      int rg = n0 + rowbase + mt * 16 + g;
      *(float2*)&y[(size_t) rg      * OO + col] =
          make_float2(acc[mt][nt][0] * sc, acc[mt][nt][1] * sc);
      *(float2*)&y[(size_t)(rg + 8) * OO + col] =
          make_float2(acc[mt][nt][2] * sc, acc[mt][nt][3] * sc);
    }
  }
}

// ------------------------- host -------------------------
extern "C" void kernel_launch(void* const* d_in, const int* in_sizes, int n_in,
                              void* d_out, int out_size) {
  const float* x  = (const float*)d_in[0];   // (B,T,I)
  const float* h0 = (const float*)d_in[1];   // (B,D)
  const float* zv = (const float*)d_in[2];   // (I,P,D)
  const float* hv = (const float*)d_in[3];   // (I,P,D)
  const float* ov = (const float*)d_in[4];   // (D,P,O)

  float* y  = (float*)d_out;                     // (B,T,O)
  float* ht = (float*)d_out + (size_t)NT * OO;   // (B,T,D)

  const int smem1 = 64 * SW1 * 4 + 3 * 16384;    // 66048
  const int smem3 = 128 * SW3 * 4 + 3 * 4096;    // 78848
  cudaFuncSetAttribute(k1_mma, cudaFuncAttributeMaxDynamicSharedMemorySize, smem1);
  cudaFuncSetAttribute(k3_mma, cudaFuncAttributeMaxDynamicSharedMemorySize, smem3);

  k0_prep<<<(32*32*32 + 64*8*32 + 255) / 256, 256>>>(zv, hv, ov);
  k1_mma<<<512, 128, smem1>>>(x);
  k2b_scan<<<BB, DD>>>(h0);
  k2c_ht<<<NSEG, DD>>>(ht);
  k3_mma<<<256, 128, smem3>>>(ht, y);
}

// round 6
// speedup vs baseline: 2.9749x; 1.3345x over previous
#include <cuda_runtime.h>
#include <cuda_fp16.h>
#include <stdint.h>

#define BB 8
#define TT 4096
#define NI 64
#define DD 128
#define OO 64
#define NT (BB*TT)          // 32768 rows
#define SEG 32
#define NSEG (NT/SEG)       // 1024 segments

// ------------------------- scratch (device globals) -------------------------
__device__ float g_hbar[NT*DD];
__device__ float g_z[NT*DD];
__device__ float g_seg[NSEG*DD];
__device__ uint4 g_bf1[32*32*32];   // stage1 B frags: [K=32][ntg=32][lane=32] {hi0,hi1,lo0,lo1}
__device__ uint4 g_bf3[64*8*32];    // stage3 B frags: [K=64][ntg=8][lane=32]

// ------------------------- helpers -------------------------
static __device__ __forceinline__ float clip7(float x){
  return fminf(fmaxf((x + 1.0f) * 3.5f, 0.0f), 7.0f);
}
static __device__ __forceinline__ float hatf(float t, float p){
  return fmaxf(0.0f, 1.0f - fabsf(t - p));
}
static __device__ __forceinline__ void pack_hl(float a, float b, uint32_t& hi, uint32_t& lo){
  __half2 h = __floats2half2_rn(a, b);
  float2  f = __half22float2(h);
  __half2 l = __floats2half2_rn(a - f.x, b - f.y);
  hi = *reinterpret_cast<uint32_t*>(&h);
  lo = *reinterpret_cast<uint32_t*>(&l);
}
static __device__ __forceinline__ void mma16816(float* c, const uint32_t* a, uint32_t b0, uint32_t b1){
  asm volatile(
    "mma.sync.aligned.m16n8k16.row.col.f32.f16.f16.f32 "
    "{%0,%1,%2,%3}, {%4,%5,%6,%7}, {%8,%9}, {%0,%1,%2,%3};"
    : "+f"(c[0]), "+f"(c[1]), "+f"(c[2]), "+f"(c[3])
    : "r"(a[0]), "r"(a[1]), "r"(a[2]), "r"(a[3]), "r"(b0), "r"(b1));
}
static __device__ __forceinline__ uint32_t smem_u32(const void* p){
  uint32_t a;
  asm("{ .reg .u64 t; cvta.to.shared.u64 t, %1; cvt.u32.u64 %0, t; }" : "=r"(a) : "l"(p));
  return a;
}
static __device__ __forceinline__ void cpa16(uint32_t sa, const void* g){
  asm volatile("cp.async.cg.shared.global [%0], [%1], 16;" :: "r"(sa), "l"(g));
}
#define CPA_COMMIT()  asm volatile("cp.async.commit_group;" ::: "memory")
#define CPA_WAIT1()   asm volatile("cp.async.wait_group 1;" ::: "memory")

// ------------------------- k0: build fragment-major B tables (x16 scale) -------------------------
__global__ void k0_prep(const float* __restrict__ zv, const float* __restrict__ hv,
                        const float* __restrict__ ov){
  int t = blockIdx.x * blockDim.x + threadIdx.x;
  if (t < 32*32*32){
    int lane = t & 31, ntg = (t >> 5) & 31, K = t >> 10;
    int q = lane & 3, g = lane >> 2;
    int n  = ntg * 8 + g;
    int kr = q * 2;
    const float* tab = (n < 128) ? hv : zv;
    int nn = n & 127;
    int i0 = 2 * K;
    float v0 = tab[((i0    )*8 + kr    )*128 + nn] * 16.0f;
    float v1 = tab[((i0    )*8 + kr + 1)*128 + nn] * 16.0f;
    float v2 = tab[((i0 + 1)*8 + kr    )*128 + nn] * 16.0f;
    float v3 = tab[((i0 + 1)*8 + kr + 1)*128 + nn] * 16.0f;
    uint4 o;
    pack_hl(v0, v1, o.x, o.z);
    pack_hl(v2, v3, o.y, o.w);
    g_bf1[t] = o;
  } else if (t < 32*32*32 + 64*8*32){
    int e = t - 32*32*32;
    int lane = e & 31, ntg = (e >> 5) & 7, K = e >> 8;
    int q = lane & 3, g = lane >> 2;
    int n  = ntg * 8 + g;
    int kr = q * 2;
    int i0 = 2 * K;
    float v0 = ov[((i0    )*8 + kr    )*64 + n] * 16.0f;
    float v1 = ov[((i0    )*8 + kr + 1)*64 + n] * 16.0f;
    float v2 = ov[((i0 + 1)*8 + kr    )*64 + n] * 16.0f;
    float v3 = ov[((i0 + 1)*8 + kr + 1)*64 + n] * 16.0f;
    uint4 o;
    pack_hl(v0, v1, o.x, o.z);
    pack_hl(v2, v3, o.y, o.w);
    g_bf3[e] = o;
  }
}

// ------------------------- K1: stage-1 HMMA GEMM (h_bar 3-pass + z 1-pass) -------------------------
// CTA: 128 thr = 4 warps; warp (mr, nc): mr -> 32 rows; every warp does 64 h-cols (3-pass)
// AND 64 z-cols (1-pass) -> balanced MMA load per SMSP. M/CTA=64 -> grid 512.
// smem: t_s 64x66 f32 (16896B) + B ring 3 x 16KB = 66048B total.
#define SW1 66
__global__ void __launch_bounds__(128) k1_mma(const float* __restrict__ x){
  extern __shared__ char smraw[];
  float* t_s = (float*)smraw;
  uint4* bbuf = (uint4*)(smraw + 64 * SW1 * 4);
  const uint32_t bbase = smem_u32(bbuf);

  const int tid = threadIdx.x;
  const int n0  = blockIdx.x * 64;

  // prologue: start copies for K=0,1 immediately (overlap with prepass)
  #pragma unroll
  for (int s = 0; s < 2; ++s){
    uint32_t sa = bbase + (uint32_t)(s * 1024 + tid) * 16u;
    const uint4* gs = g_bf1 + (size_t)s * 1024 + tid;
    #pragma unroll
    for (int j = 0; j < 8; ++j) cpa16(sa + j * 128 * 16, gs + j * 128);
    CPA_COMMIT();
  }

  // prepass: t = clipped grid coords for the 64x64 x-tile
  #pragma unroll
  for (int e = tid; e < 64 * 16; e += 128){
    int r = e >> 4, c4 = e & 15;
    float4 v = ((const float4*)(x + (size_t)(n0 + r) * NI))[c4];
    float* d = &t_s[r * SW1 + c4 * 4];
    d[0] = clip7(v.x); d[1] = clip7(v.y); d[2] = clip7(v.z); d[3] = clip7(v.w);
  }
  __syncthreads();

  const int w = tid >> 5, lane = tid & 31;
  const int mr = w & 1, nc = w >> 1;
  const int rowbase = mr * 32;
  const int q = lane & 3, g = lane >> 2;
  const float p0 = (float)(2 * q);

  // acc[mt][nt][*]: nt 0-7 = h cols (nc*64 + nt*8), nt 8-15 = z cols (nc*64 + (nt-8)*8)
  float acc[2][16][4];
  #pragma unroll
  for (int a = 0; a < 2; ++a)
    #pragma unroll
    for (int b = 0; b < 16; ++b)
      #pragma unroll
      for (int c = 0; c < 4; ++c) acc[a][b][c] = 0.0f;

  #pragma unroll 1
  for (int K = 0; K < 32; ++K){
    // A-build first: overlaps in-flight cp.async
    const int i0 = 2 * K;
    uint32_t ah[2][4], al[2][4];
    #pragma unroll
    for (int mt = 0; mt < 2; ++mt){
      int r0 = rowbase + mt * 16 + g;
      float2 tA = *(const float2*)&t_s[ r0      * SW1 + i0];
      float2 tB = *(const float2*)&t_s[(r0 + 8) * SW1 + i0];
      pack_hl(hatf(tA.x, p0), hatf(tA.x, p0 + 1.0f), ah[mt][0], al[mt][0]);
      pack_hl(hatf(tB.x, p0), hatf(tB.x, p0 + 1.0f), ah[mt][1], al[mt][1]);
      pack_hl(hatf(tA.y, p0), hatf(tA.y, p0 + 1.0f), ah[mt][2], al[mt][2]);
      pack_hl(hatf(tB.y, p0), hatf(tB.y, p0 + 1.0f), ah[mt][3], al[mt][3]);
    }

    CPA_WAIT1();          // stage K landed
    __syncthreads();      // visible to all warps; prior stage fully consumed

    if (K + 2 < 32){      // issue copy for K+2 into ring slot (K+2)%3
      int s = (K + 2) % 3;
      uint32_t sa = bbase + (uint32_t)(s * 1024 + tid) * 16u;
      const uint4* gs = g_bf1 + (size_t)(K + 2) * 1024 + tid;
      #pragma unroll
      for (int j = 0; j < 8; ++j) cpa16(sa + j * 128 * 16, gs + j * 128);
      CPA_COMMIT();
    }

    // h columns: ntg = nc*8 + nt (cols 0-127), 3 passes
    const uint4* bsh = bbuf + (K % 3) * 1024 + (nc * 8) * 32 + lane;
    // z columns: ntg = 16 + nc*8 + nt (cols 128-255), 1 pass (hi only)
    const uint4* bsz = bbuf + (K % 3) * 1024 + (16 + nc * 8) * 32 + lane;
    #pragma unroll
    for (int nt = 0; nt < 8; ++nt){
      uint4 bv = bsh[nt * 32];
      #pragma unroll
      for (int mt = 0; mt < 2; ++mt){
        mma16816(acc[mt][nt], ah[mt], bv.x, bv.y);   // Ah*Bh
        mma16816(acc[mt][nt], ah[mt], bv.z, bv.w);   // Ah*Bl
        mma16816(acc[mt][nt], al[mt], bv.x, bv.y);   // Al*Bh
      }
      uint2 bz = *(const uint2*)&bsz[nt * 32];       // hi pair only
      #pragma unroll
      for (int mt = 0; mt < 2; ++mt)
        mma16816(acc[mt][nt + 8], ah[mt], bz.x, bz.y);  // z: Ah*Bh only
    }
  }

  // epilogue: scale 1/16; h -> g_hbar + segment sums; z -> sigmoid -> g_z
  const float sc = 0.0625f;
  const int sgi = blockIdx.x * 2 + mr;
  #pragma unroll
  for (int nt = 0; nt < 8; ++nt){
    const int col = nc * 64 + nt * 8 + q * 2;
    float s0 = 0.0f, s1 = 0.0f;
    #pragma unroll
    for (int mt = 0; mt < 2; ++mt){
      // h part
      float c0 = acc[mt][nt][0] * sc, c1 = acc[mt][nt][1] * sc;
      float c2 = acc[mt][nt][2] * sc, c3 = acc[mt][nt][3] * sc;
      int rg = n0 + rowbase + mt * 16 + g;
      *(float2*)&g_hbar[(size_t) rg      * DD + col] = make_float2(c0, c1);
      *(float2*)&g_hbar[(size_t)(rg + 8) * DD + col] = make_float2(c2, c3);
      s0 += c0 + c2; s1 += c1 + c3;
      // z part
      float z0 = acc[mt][nt + 8][0] * sc, z1 = acc[mt][nt + 8][1] * sc;
      float z2 = acc[mt][nt + 8][2] * sc, z3 = acc[mt][nt + 8][3] * sc;
      z0 = 1.0f / (1.0f + __expf(-z0)); z1 = 1.0f / (1.0f + __expf(-z1));
      z2 = 1.0f / (1.0f + __expf(-z2)); z3 = 1.0f / (1.0f + __expf(-z3));
      *(float2*)&g_z[(size_t) rg      * DD + col] = make_float2(z0, z1);
      *(float2*)&g_z[(size_t)(rg + 8) * DD + col] = make_float2(z2, z3);
    }
    #pragma unroll
    for (int off = 4; off < 32; off <<= 1){
      s0 += __shfl_xor_sync(0xFFFFFFFFu, s0, off);
      s1 += __shfl_xor_sync(0xFFFFFFFFu, s1, off);
    }
    if (g == 0)
      *(float2*)&g_seg[(size_t)sgi * DD + col] = make_float2(s0, s1);
  }
}

// ------------------------- k2b: exclusive scan over segments (per batch) -------------------------
__global__ void k2b_scan(const float* __restrict__ h0){
  int b = blockIdx.x, d = threadIdx.x;
  float run = h0[b * DD + d];
  float* p = g_seg + (size_t)b * (TT / SEG) * DD + d;
  #pragma unroll 1
  for (int gq = 0; gq < (TT / SEG) / 8; ++gq){
    float v[8];
    #pragma unroll
    for (int j = 0; j < 8; ++j) v[j] = p[(gq * 8 + j) * DD];
    #pragma unroll
    for (int j = 0; j < 8; ++j){ float t = v[j]; p[(gq * 8 + j) * DD] = run; run += t; }
  }
}

// ------------------------- k2c: ht = c + z*(h_bar - c) -------------------------
__global__ void __launch_bounds__(128) k2c_ht(float* __restrict__ out_ht){
  int si = blockIdx.x, d = threadIdx.x;
  float c = g_seg[(size_t)si * DD + d];
  size_t base = (size_t)si * SEG * DD + d;
  #pragma unroll
  for (int t0 = 0; t0 < SEG; t0 += 8){
    float hb[8], zz[8];
    #pragma unroll
    for (int j = 0; j < 8; ++j){
      hb[j] = g_hbar[base + (size_t)(t0 + j) * DD];
      zz[j] = g_z  [base + (size_t)(t0 + j) * DD];
    }
    #pragma unroll
    for (int j = 0; j < 8; ++j){
      c += hb[j];
      out_ht[base + (size_t)(t0 + j) * DD] = fmaf(zz[j], hb[j] - c, c);
    }
  }
}

// ------------------------- K3: stage-3 HMMA GEMM (y), 2-pass -------------------------
// CTA: 128 thr = 4 warps; warp mr -> 32 rows, all 64 cols. M/CTA=128 -> grid 256.
// smem: t3_s 128x130 f32 (66560B) + B ring 3 x 4KB = 78848B total.
#define SW3 130
__global__ void __launch_bounds__(128) k3_mma(const float* __restrict__ ht,
                                              float* __restrict__ y){
  extern __shared__ char smraw[];
  float* t3_s = (float*)smraw;
  uint4* bbuf = (uint4*)(smraw + 128 * SW3 * 4);
  const uint32_t bbase = smem_u32(bbuf);

  const int tid = threadIdx.x;
  const int n0  = blockIdx.x * 128;

  #pragma unroll
  for (int s = 0; s < 2; ++s){
    uint32_t sa = bbase + (uint32_t)(s * 256 + tid) * 16u;
    const uint4* gs = g_bf3 + (size_t)s * 256 + tid;
    #pragma unroll
    for (int j = 0; j < 2; ++j) cpa16(sa + j * 128 * 16, gs + j * 128);
    CPA_COMMIT();
  }

  #pragma unroll 1
  for (int e = tid; e < 128 * 32; e += 128){
    int r = e >> 5, c4 = e & 31;
    float4 v = ((const float4*)(ht + (size_t)(n0 + r) * DD))[c4];
    float* d = &t3_s[r * SW3 + c4 * 4];
    d[0] = clip7(v.x); d[1] = clip7(v.y); d[2] = clip7(v.z); d[3] = clip7(v.w);
  }
  __syncthreads();

  const int mr = tid >> 5, lane = tid & 31;
  const int rowbase = mr * 32;
  const int q = lane & 3, g = lane >> 2;
  const float p0 = (float)(2 * q);

  float acc[2][8][4];
  #pragma unroll
  for (int a = 0; a < 2; ++a)
    #pragma unroll
    for (int b = 0; b < 8; ++b)
      #pragma unroll
      for (int c = 0; c < 4; ++c) acc[a][b][c] = 0.0f;

  #pragma unroll 1
  for (int K = 0; K < 64; ++K){
    const int i0 = 2 * K;
    uint32_t ah[2][4], al[2][4];
    #pragma unroll
    for (int mt = 0; mt < 2; ++mt){
      int r0 = rowbase + mt * 16 + g;
      float2 tA = *(const float2*)&t3_s[ r0      * SW3 + i0];
      float2 tB = *(const float2*)&t3_s[(r0 + 8) * SW3 + i0];
      pack_hl(hatf(tA.x, p0), hatf(tA.x, p0 + 1.0f), ah[mt][0], al[mt][0]);
      pack_hl(hatf(tB.x, p0), hatf(tB.x, p0 + 1.0f), ah[mt][1], al[mt][1]);
      pack_hl(hatf(tA.y, p0), hatf(tA.y, p0 + 1.0f), ah[mt][2], al[mt][2]);
      pack_hl(hatf(tB.y, p0), hatf(tB.y, p0 + 1.0f), ah[mt][3], al[mt][3]);
    }

    CPA_WAIT1();
    __syncthreads();

    if (K + 2 < 64){
      int s = (K + 2) % 3;
      uint32_t sa = bbase + (uint32_t)(s * 256 + tid) * 16u;
      const uint4* gs = g_bf3 + (size_t)(K + 2) * 256 + tid;
      #pragma unroll
      for (int j = 0; j < 2; ++j) cpa16(sa + j * 128 * 16, gs + j * 128);
      CPA_COMMIT();
    }

    const uint4* bs = bbuf + (K % 3) * 256 + lane;
    uint4 bv = bs[0];
    #pragma unroll
    for (int nt = 0; nt < 8; ++nt){
      uint4 nb;
      if (nt < 7) nb = bs[(nt + 1) * 32];
      #pragma unroll
      for (int mt = 0; mt < 2; ++mt){
        mma16816(acc[mt][nt], ah[mt], bv.x, bv.y);   // Ah*Bh
        mma16816(acc[mt][nt], al[mt], bv.x, bv.y);   // Al*Bh (drop Ah*Bl: B-quant ~1.2e-4)
      }
      if (nt < 7) bv = nb;
    }
  }

  const float sc = 0.0625f;
  #pragma unroll
  for (int nt = 0; nt < 8; ++nt){
    const int col = nt * 8 + q * 2;
    #pragma unroll
    for (int mt = 0; mt < 2; ++mt){
      int rg = n0 + rowbase + mt * 16 + g;
      *(float2*)&y[(size_t) rg      * OO + col] =
          make_float2(acc[mt][nt][0] * sc, acc[mt][nt][1] * sc);
      *(float2*)&y[(size_t)(rg + 8) * OO + col] =
          make_float2(acc[mt][nt][2] * sc, acc[mt][nt][3] * sc);
    }
  }
}

// ------------------------- host -------------------------
extern "C" void kernel_launch(void* const* d_in, const int* in_sizes, int n_in,
                              void* d_out, int out_size) {
  const float* x  = (const float*)d_in[0];   // (B,T,I)
  const float* h0 = (const float*)d_in[1];   // (B,D)
  const float* zv = (const float*)d_in[2];   // (I,P,D)
  const float* hv = (const float*)d_in[3];   // (I,P,D)
  const float* ov = (const float*)d_in[4];   // (D,P,O)

  float* y  = (float*)d_out;                     // (B,T,O)
  float* ht = (float*)d_out + (size_t)NT * OO;   // (B,T,D)

  const int smem1 = 64 * SW1 * 4 + 3 * 16384;    // 66048
  const int smem3 = 128 * SW3 * 4 + 3 * 4096;    // 78848
  cudaFuncSetAttribute(k1_mma, cudaFuncAttributeMaxDynamicSharedMemorySize, smem1);
  cudaFuncSetAttribute(k3_mma, cudaFuncAttributeMaxDynamicSharedMemorySize, smem3);

  k0_prep<<<(32*32*32 + 64*8*32 + 255) / 256, 256>>>(zv, hv, ov);
  k1_mma<<<512, 128, smem1>>>(x);
  k2b_scan<<<BB, DD>>>(h0);
  k2c_ht<<<NSEG, DD>>>(ht);
  k3_mma<<<256, 128, smem3>>>(ht, y);
}